// round 1
// baseline (speedup 1.0000x reference)
#include <cuda_runtime.h>

// SoftBoundDDM_RT: 4096 trials x 2000-step leaky-DDM recurrence + soft bounds.
// One block per trial; 8 timesteps per thread; affine block scan for the
// linear recurrence e[t] = DECAY*e[t-1] + u[t-1].
//
// Inputs (metadata order): stimulus (N*T f32), noise (N*T f32),
//   a, z, drift_gain, drift_offset, beta (1-elem f32 each).
// Output: concat [dv | h1 | h0], each (N, T) f32, total 3*N*T.

constexpr int   N_T   = 2000;
constexpr int   CH    = 8;           // timesteps per thread
constexpr int   TPB   = 256;         // 250 active threads (250*8 = 2000)
constexpr float DT    = 0.001f;
constexpr float LEAK  = 0.01f;
constexpr float TC    = 0.01f;       // TIME_CONSTANT
constexpr float DECAY = 1.0f - LEAK * DT;            // 0.99999
constexpr float SQVDT = 0.03162277660168379332f;     // sqrt(VARIANCE*DT)

__device__ __forceinline__ float sigm(float x) {
    // 1/(1+exp(-x)); saturates to exact 0/1 at extremes like the reference.
    return 1.0f / (1.0f + __expf(-x));
}

__global__ __launch_bounds__(TPB)
void ddm_kernel(const float* __restrict__ stim,
                const float* __restrict__ noise,
                const float* __restrict__ pa,
                const float* __restrict__ pz,
                const float* __restrict__ pg,
                const float* __restrict__ po,
                const float* __restrict__ pb,
                float* __restrict__ out,
                long long total_elems)      // n_trials * N_T
{
    const int trial = blockIdx.x;
    const int t     = threadIdx.x;
    const int lane  = t & 31;
    const int warp  = t >> 5;

    const float a    = __ldg(pa);
    const float z    = __ldg(pz);
    const float g    = __ldg(pg);
    const float off  = __ldg(po);
    const float beta = __ldg(pb);

    const float e0     = z * a;                    // starting point
    const float cstim  = g * DT;
    const float cconst = off * DT + LEAK * e0 * DT;
    const float D2 = DECAY * DECAY, D4 = D2 * D2, D8 = D4 * D4;

    const size_t base  = (size_t)trial * N_T;
    const bool active  = (t * CH < N_T);           // t < 250

    // ---- load this thread's 8 u-values (fully coalesced float4) ----
    float u[CH];
    if (active) {
        const float4 s0 = *reinterpret_cast<const float4*>(stim  + base + t * CH);
        const float4 s1 = *reinterpret_cast<const float4*>(stim  + base + t * CH + 4);
        const float4 n0 = *reinterpret_cast<const float4*>(noise + base + t * CH);
        const float4 n1 = *reinterpret_cast<const float4*>(noise + base + t * CH + 4);
        u[0] = fmaf(cstim, s0.x, fmaf(SQVDT, n0.x, cconst));
        u[1] = fmaf(cstim, s0.y, fmaf(SQVDT, n0.y, cconst));
        u[2] = fmaf(cstim, s0.z, fmaf(SQVDT, n0.z, cconst));
        u[3] = fmaf(cstim, s0.w, fmaf(SQVDT, n0.w, cconst));
        u[4] = fmaf(cstim, s1.x, fmaf(SQVDT, n1.x, cconst));
        u[5] = fmaf(cstim, s1.y, fmaf(SQVDT, n1.y, cconst));
        u[6] = fmaf(cstim, s1.z, fmaf(SQVDT, n1.z, cconst));
        u[7] = fmaf(cstim, s1.w, fmaf(SQVDT, n1.w, cconst));
    } else {
        #pragma unroll
        for (int k = 0; k < CH; k++) u[k] = 0.0f;
    }

    // ---- local affine transform of this chunk: e -> A*e + B ----
    float B = 0.0f;
    #pragma unroll
    for (int k = 0; k < CH; k++) B = fmaf(DECAY, B, u[k]);
    float A = active ? D8 : 1.0f;
    if (!active) B = 0.0f;

    // ---- inclusive warp scan of affine maps (earlier-first composition) ----
    float Ai = A, Bi = B;
    #pragma unroll
    for (int d = 1; d < 32; d <<= 1) {
        float Ao = __shfl_up_sync(0xffffffffu, Ai, d);
        float Bo = __shfl_up_sync(0xffffffffu, Bi, d);
        if (lane >= d) { Bi = fmaf(Ai, Bo, Bi); Ai *= Ao; }
    }

    __shared__ float sA[TPB / 32];
    __shared__ float sB[TPB / 32];
    if (lane == 31) { sA[warp] = Ai; sB[warp] = Bi; }
    __syncthreads();

    // exclusive prefix over preceding warps (<=7 serial composes, cheap)
    float Aw = 1.0f, Bw = 0.0f;
    for (int w = 0; w < warp; w++) { Bw = fmaf(sA[w], Bw, sB[w]); Aw *= sA[w]; }

    // exclusive within-warp prefix = lane-1's inclusive
    float Ae = __shfl_up_sync(0xffffffffu, Ai, 1);
    float Be = __shfl_up_sync(0xffffffffu, Bi, 1);
    if (lane == 0) { Ae = 1.0f; Be = 0.0f; }

    const float Aex = Aw * Ae;
    const float Bex = fmaf(Ae, Bw, Be);
    float ev = fmaf(Aex, e0, Bex);     // evidence at time index t*CH

    if (!active) return;

    // ---- compute dv, h1, h0 for the 8 timesteps ----
    float dvv[CH], h1v[CH], h0v[CH];
    const float nba = -beta * a;
    #pragma unroll
    for (int k = 0; k < CH; k++) {
        if (k > 0) ev = fmaf(DECAY, ev, u[k - 1]);   // exact sequential step
        const float urg = (float)(t * CH + k) * TC;
        const float dv  = fmaf(urg, ev - e0, e0);
        dvv[k] = dv;
        h1v[k] = sigm(fmaf(beta, dv, nba));          // sigmoid(beta*(dv - a))
        h0v[k] = sigm(-beta * dv);                   // sigmoid(-beta*dv)
    }

    // ---- coalesced float4 stores ----
    float* dvout = out + base + t * CH;
    float* h1out = out + (size_t)total_elems + base + t * CH;
    float* h0out = out + 2 * (size_t)total_elems + base + t * CH;
    *reinterpret_cast<float4*>(dvout)     = make_float4(dvv[0], dvv[1], dvv[2], dvv[3]);
    *reinterpret_cast<float4*>(dvout + 4) = make_float4(dvv[4], dvv[5], dvv[6], dvv[7]);
    *reinterpret_cast<float4*>(h1out)     = make_float4(h1v[0], h1v[1], h1v[2], h1v[3]);
    *reinterpret_cast<float4*>(h1out + 4) = make_float4(h1v[4], h1v[5], h1v[6], h1v[7]);
    *reinterpret_cast<float4*>(h0out)     = make_float4(h0v[0], h0v[1], h0v[2], h0v[3]);
    *reinterpret_cast<float4*>(h0out + 4) = make_float4(h0v[4], h0v[5], h0v[6], h0v[7]);
}

extern "C" void kernel_launch(void* const* d_in, const int* in_sizes, int n_in,
                              void* d_out, int out_size)
{
    const float* stim  = (const float*)d_in[0];
    const float* noise = (const float*)d_in[1];
    const float* pa    = (const float*)d_in[2];
    const float* pz    = (const float*)d_in[3];
    const float* pg    = (const float*)d_in[4];
    const float* po    = (const float*)d_in[5];
    const float* pb    = (const float*)d_in[6];
    float* out = (float*)d_out;

    const long long total = in_sizes[0];          // n_trials * N_T
    const int n_trials = (int)(total / N_T);

    ddm_kernel<<<n_trials, TPB>>>(stim, noise, pa, pz, pg, po, pb, out, total);
}